// round 9
// baseline (speedup 1.0000x reference)
#include <cuda_runtime.h>
#include <cuda_fp16.h>
#include <math.h>
#include <float.h>

#define NN 100000
#define EE 1600000
#define HH 64
#define CC 10
#define CAP 96                       // per-node neighbor bucket (Poisson(16), max~50)

// ---------------- static device scratch ----------------
__device__ int          g_deg[NN];
__device__ int          g_col[NN * CAP];      // padded neighbor lists
__device__ float        g_h[NN * HH];         // fp32 node features
__device__ unsigned int g_hh[NN * 32];        // fp16x2 shadow copy of h
__device__ unsigned int g_aggh[NN * 32];      // fp16x2 segment-max (exact: max of fp16s)
__device__ int          g_odd_nonzero;

// ---------------- zero degrees + edge dtype detection ----------------
// int64 edge ids < 2^31 -> every odd 32-bit word is 0.
__global__ void zerodetect_kernel(const unsigned int* __restrict__ w) {
    int i = blockIdx.x * blockDim.x + threadIdx.x;
    if (i < NN) g_deg[i] = 0;
    if (i == 0) g_odd_nonzero = 0;
    if (i < 65536) {
        unsigned int v = w[2 * i + 1];
        if (v) atomicOr(&g_odd_nonzero, 1);
    }
}

// ---------------- scan-free CSR: scatter into padded buckets ----------------
__global__ void buildcol_kernel(const void* __restrict__ ei) {
    int i = blockIdx.x * blockDim.x + threadIdx.x;
    if (i >= EE) return;
    int s, d;
    if (g_odd_nonzero == 0) {
        s = (int)((const long long*)ei)[i];
        d = (int)((const long long*)ei)[EE + i];
    } else {
        s = ((const int*)ei)[i];
        d = ((const int*)ei)[EE + i];
    }
    int pos = atomicAdd(&g_deg[d], 1);
    if (pos < CAP) g_col[d * CAP + pos] = s;
}

// ---------------- segment max over fp16 shadow: 2 nodes per warp ----------------
__global__ void segmax_kernel() {
    int gw   = (blockIdx.x * blockDim.x + threadIdx.x) >> 5;
    int lane = threadIdx.x & 31;
    int n0 = gw * 2, n1 = gw * 2 + 1;
    if (n0 >= NN) return;
    int cnt0 = min(g_deg[n0], CAP);
    int cnt1 = (n1 < NN) ? min(g_deg[n1], CAP) : 0;
    const int* col0 = g_col + n0 * CAP;
    const int* col1 = g_col + n1 * CAP;

    __half2 a0 = __floats2half2_rn(-65504.f, -65504.f);
    __half2 a1 = a0;
    int b0 = 0, b1 = 0;
    while (b0 < cnt0 || b1 < cnt1) {
        int c0 = min(32, cnt0 - b0);        // may be <= 0
        int c1 = min(32, cnt1 - b1);
        int s0 = 0, s1 = 0;
        if (lane < c0) s0 = col0[b0 + lane];
        if (lane < c1) s1 = col1[b1 + lane];
        int cm = max(c0, c1);
        for (int e = 0; e < cm; e++) {
            int v0 = __shfl_sync(0xffffffffu, s0, e);
            int v1 = __shfl_sync(0xffffffffu, s1, e);
            if (e < c0) {
                unsigned p = g_hh[v0 * 32 + lane];
                a0 = __hmax2(a0, *(__half2*)&p);
            }
            if (e < c1) {
                unsigned p = g_hh[v1 * 32 + lane];
                a1 = __hmax2(a1, *(__half2*)&p);
            }
        }
        b0 += 32; b1 += 32;
    }

    if (cnt0 == 0) a0 = __floats2half2_rn(0.f, 0.f);
    g_aggh[n0 * 32 + lane] = *(unsigned*)&a0;
    if (n1 < NN) {
        if (cnt1 == 0) a1 = __floats2half2_rn(0.f, 0.f);
        g_aggh[n1 * 32 + lane] = *(unsigned*)&a1;
    }
}

// ---------------- 64-wide fp32 GEMM: C = (A [+ fp16 agg]) @ W + b ----------------
// Also emits a packed fp16 shadow copy of C for the next layer's gather.
template <bool ADD>
__global__ void gemm64_kernel(const float* __restrict__ A,
                              const unsigned int* __restrict__ Ah,  // fp16x2 agg
                              const float* __restrict__ W,
                              const float* __restrict__ bias,
                              float* __restrict__ Cm,
                              unsigned int* __restrict__ Ch, int n) {
    __shared__ float As[64][68];
    __shared__ float Ws[64][68];
    int tid = threadIdx.x;
    int block_row = blockIdx.x * 64;

    for (int i = tid; i < 1024; i += 256) {
        int k = i >> 4, j4 = i & 15;
        float4 v = ((const float4*)W)[i];
        *(float4*)&Ws[k][j4 * 4] = v;
    }
    for (int i = tid; i < 1024; i += 256) {
        int m = i >> 4, k4 = i & 15;
        int row = block_row + m;
        float4 v = make_float4(0.f, 0.f, 0.f, 0.f);
        if (row < n) {
            v = ((const float4*)A)[row * 16 + k4];
            if (ADD) {
                uint2 ph = ((const uint2*)Ah)[row * 16 + k4];
                float2 u0 = __half22float2(*(__half2*)&ph.x);
                float2 u1 = __half22float2(*(__half2*)&ph.y);
                v.x += u0.x; v.y += u0.y; v.z += u1.x; v.w += u1.y;
            }
        }
        *(float4*)&As[m][k4 * 4] = v;
    }
    __syncthreads();

    int tx = tid & 15, ty = tid >> 4;
    int m0 = ty * 4, j0 = tx * 4;
    float acc[4][4];
#pragma unroll
    for (int i = 0; i < 4; i++)
#pragma unroll
        for (int j = 0; j < 4; j++) acc[i][j] = 0.f;

#pragma unroll 16
    for (int k = 0; k < 64; k++) {
        float b0 = Ws[k][j0], b1 = Ws[k][j0 + 1], b2 = Ws[k][j0 + 2], b3 = Ws[k][j0 + 3];
#pragma unroll
        for (int i = 0; i < 4; i++) {
            float a = As[m0 + i][k];
            acc[i][0] = fmaf(a, b0, acc[i][0]);
            acc[i][1] = fmaf(a, b1, acc[i][1]);
            acc[i][2] = fmaf(a, b2, acc[i][2]);
            acc[i][3] = fmaf(a, b3, acc[i][3]);
        }
    }
    float bb0 = bias[j0], bb1 = bias[j0 + 1], bb2 = bias[j0 + 2], bb3 = bias[j0 + 3];
#pragma unroll
    for (int i = 0; i < 4; i++) {
        int row = block_row + m0 + i;
        if (row < n) {
            float4 o = make_float4(acc[i][0] + bb0, acc[i][1] + bb1,
                                   acc[i][2] + bb2, acc[i][3] + bb3);
            ((float4*)Cm)[row * 16 + (j0 >> 2)] = o;
            __half2 p0 = __floats2half2_rn(o.x, o.y);
            __half2 p1 = __floats2half2_rn(o.z, o.w);
            uint2 packed = make_uint2(*(unsigned int*)&p0, *(unsigned int*)&p1);
            ((uint2*)Ch)[row * 16 + (j0 >> 2)] = packed;
        }
    }
}

// ---------------- decoder + log-softmax ----------------
__global__ void decoder_kernel(const float* __restrict__ dw,
                               const float* __restrict__ db,
                               float* __restrict__ out, int n) {
    __shared__ float Ws[HH * CC];
    __shared__ float bs[CC];
    int tid = threadIdx.x;
    for (int i = tid; i < HH * CC; i += blockDim.x) Ws[i] = dw[i];
    if (tid < CC) bs[tid] = db[tid];
    __syncthreads();
    int node = blockIdx.x * blockDim.x + tid;
    if (node >= n) return;
    float acc[CC];
#pragma unroll
    for (int c = 0; c < CC; c++) acc[c] = bs[c];
    const float4* hp = (const float4*)(g_h + node * HH);
#pragma unroll
    for (int k4 = 0; k4 < 16; k4++) {
        float4 v = hp[k4];
        int kb = k4 * 4;
#pragma unroll
        for (int c = 0; c < CC; c++)
            acc[c] += v.x * Ws[(kb + 0) * CC + c] + v.y * Ws[(kb + 1) * CC + c] +
                      v.z * Ws[(kb + 2) * CC + c] + v.w * Ws[(kb + 3) * CC + c];
    }
    float mx = acc[0];
#pragma unroll
    for (int c = 1; c < CC; c++) mx = fmaxf(mx, acc[c]);
    float s = 0.f;
#pragma unroll
    for (int c = 0; c < CC; c++) s += expf(acc[c] - mx);
    float lse = mx + logf(s);
#pragma unroll
    for (int c = 0; c < CC; c++) out[node * CC + c] = acc[c] - lse;
}

// ---------------- launch ----------------
extern "C" void kernel_launch(void* const* d_in, const int* in_sizes, int n_in,
                              void* d_out, int out_size) {
    const float* x      = (const float*)d_in[0];
    const void*  ei     = d_in[1];
    const float* enc_w  = (const float*)d_in[3];
    const float* enc_b  = (const float*)d_in[4];
    const float* proc_w = (const float*)d_in[5];
    const float* proc_b = (const float*)d_in[6];
    const float* dec_w  = (const float*)d_in[7];
    const float* dec_b  = (const float*)d_in[8];
    float* out = (float*)d_out;

    float* hptr = nullptr;
    unsigned int* hhptr = nullptr;
    unsigned int* agghptr = nullptr;
    cudaGetSymbolAddress((void**)&hptr, g_h);
    cudaGetSymbolAddress((void**)&hhptr, g_hh);
    cudaGetSymbolAddress((void**)&agghptr, g_aggh);

    const int n = NN;

    // fork: encoder GEMM runs concurrently with CSR build
    cudaStream_t s2;
    cudaStreamCreateWithFlags(&s2, cudaStreamNonBlocking);
    cudaEvent_t e0, e1;
    cudaEventCreateWithFlags(&e0, cudaEventDisableTiming);
    cudaEventCreateWithFlags(&e1, cudaEventDisableTiming);
    cudaEventRecord(e0, 0);
    cudaStreamWaitEvent(s2, e0, 0);

    // encoder on s2 (emits fp32 h + fp16 shadow)
    gemm64_kernel<false><<<(n + 63) / 64, 256, 0, s2>>>(x, nullptr, enc_w, enc_b,
                                                        hptr, hhptr, n);
    cudaEventRecord(e1, s2);

    // scan-free CSR build on capture stream
    zerodetect_kernel<<<(NN + 255) / 256, 256>>>((const unsigned int*)ei);
    buildcol_kernel<<<(EE + 255) / 256, 256>>>(ei);

    // join: need both CSR and encoder before first segmax
    cudaStreamWaitEvent(0, e1, 0);

    // 6 GIN layers
    for (int it = 0; it < 6; it++) {
        segmax_kernel<<<((NN / 2) * 32 + 255) / 256, 256>>>();
        gemm64_kernel<true><<<(n + 63) / 64, 256>>>(hptr, agghptr, proc_w, proc_b,
                                                    hptr, hhptr, n);
    }

    // decoder + log-softmax
    decoder_kernel<<<(n + 127) / 128, 128>>>(dec_w, dec_b, out, n);
}

// round 10
// speedup vs baseline: 1.0742x; 1.0742x over previous
#include <cuda_runtime.h>
#include <cuda_fp16.h>
#include <math.h>
#include <float.h>

#define NN 100000
#define EE 1600000
#define HH 64
#define CC 10
#define SCAN_BLK 1024
#define SCAN_NBLK ((NN + SCAN_BLK - 1) / SCAN_BLK)   // 98

// ---------------- static device scratch ----------------
__device__ int          g_dst[EE];
__device__ int          g_col[EE];
__device__ int          g_deg[NN];
__device__ int          g_rowptr[NN + 1];
__device__ int          g_cursor[NN];
__device__ int          g_blocksum[SCAN_NBLK];
__device__ float        g_h[NN * HH];        // fp32 node features
__device__ unsigned int g_hh[NN * 32];       // fp16x2 shadow copy of h
__device__ unsigned int g_aggh[NN * 32];     // fp16x2 segment-max (exact)
__device__ int          g_odd_nonzero;

__device__ __forceinline__ uint4 hmax4(uint4 a, uint4 b) {
    uint4 r;
    *(__half2*)&r.x = __hmax2(*(__half2*)&a.x, *(__half2*)&b.x);
    *(__half2*)&r.y = __hmax2(*(__half2*)&a.y, *(__half2*)&b.y);
    *(__half2*)&r.z = __hmax2(*(__half2*)&a.z, *(__half2*)&b.z);
    *(__half2*)&r.w = __hmax2(*(__half2*)&a.w, *(__half2*)&b.w);
    return r;
}

// ---------------- setup: zero degrees + edge dtype detection ----------------
// int64 edge ids < 2^31 -> every odd 32-bit word is 0.
__global__ void zerodetect_kernel(const unsigned int* __restrict__ w) {
    int i = blockIdx.x * blockDim.x + threadIdx.x;
    if (i < NN) g_deg[i] = 0;
    if (i == 0) g_odd_nonzero = 0;
    if (i < 65536) {
        unsigned int v = w[2 * i + 1];
        if (v) atomicOr(&g_odd_nonzero, 1);
    }
}

__global__ void convert_kernel(const void* __restrict__ ei) {
    int i = blockIdx.x * blockDim.x + threadIdx.x;
    if (i >= EE) return;
    int d;
    if (g_odd_nonzero == 0) d = (int)((const long long*)ei)[EE + i];
    else                    d = ((const int*)ei)[EE + i];
    g_dst[i] = d;
    atomicAdd(&g_deg[d], 1);
}

// ---------------- multi-block exclusive scan ----------------
__global__ void scan_phase1() {
    __shared__ int warp_sums[32];
    int tid = threadIdx.x;
    int i = blockIdx.x * SCAN_BLK + tid;
    int v = (i < NN) ? g_deg[i] : 0;
    int lane = tid & 31, wid = tid >> 5;

    int incl = v;
#pragma unroll
    for (int off = 1; off < 32; off <<= 1) {
        int t = __shfl_up_sync(0xffffffffu, incl, off);
        if (lane >= off) incl += t;
    }
    if (lane == 31) warp_sums[wid] = incl;
    __syncthreads();
    if (wid == 0) {
        int ws = warp_sums[lane];
        int wincl = ws;
#pragma unroll
        for (int off = 1; off < 32; off <<= 1) {
            int t = __shfl_up_sync(0xffffffffu, wincl, off);
            if (lane >= off) wincl += t;
        }
        warp_sums[lane] = wincl - ws;
        if (lane == 31) g_blocksum[blockIdx.x] = wincl;
    }
    __syncthreads();
    int excl = incl - v + warp_sums[wid];
    if (i < NN) g_rowptr[i] = excl;
}

__global__ void scan_phase2() {
    __shared__ int ws4[4];
    __shared__ int total;
    int tid = threadIdx.x;            // 128 threads
    int v = (tid < SCAN_NBLK) ? g_blocksum[tid] : 0;
    int lane = tid & 31, wid = tid >> 5;
    int incl = v;
#pragma unroll
    for (int off = 1; off < 32; off <<= 1) {
        int t = __shfl_up_sync(0xffffffffu, incl, off);
        if (lane >= off) incl += t;
    }
    if (lane == 31) ws4[wid] = incl;
    __syncthreads();
    if (tid == 0) {
        int c = 0;
        for (int w = 0; w < 4; w++) { int t = ws4[w]; ws4[w] = c; c += t; }
        total = c;
    }
    __syncthreads();
    if (tid < SCAN_NBLK) g_blocksum[tid] = incl - v + ws4[wid];
    if (tid == 0) g_rowptr[NN] = total;
}

__global__ void scan_phase3() {
    int i = blockIdx.x * SCAN_BLK + threadIdx.x;
    if (i >= NN) return;
    int r = g_rowptr[i] + g_blocksum[blockIdx.x];
    g_rowptr[i] = r;
    g_cursor[i] = r;
}

__global__ void scatter_kernel(const void* __restrict__ ei) {
    int i = blockIdx.x * blockDim.x + threadIdx.x;
    if (i >= EE) return;
    int s;
    if (g_odd_nonzero == 0) s = (int)((const long long*)ei)[i];
    else                    s = ((const int*)ei)[i];
    int d = g_dst[i];
    int pos = atomicAdd(&g_cursor[d], 1);
    g_col[pos] = s;
}

// ---------------- segment max: 1 warp per node, 4 edges x 8 lanes ----------------
// Each group of 8 lanes handles one edge; lane loads a 16B uint4 chunk of the
// neighbor's 128B fp16 row (one LDG.128). ~1.75 issue slots per edge instead
// of ~5 for the scalar-gather variant. Tail: cross-group shfl_xor max.
__global__ void segmax_kernel() {
    int gw   = (blockIdx.x * blockDim.x + threadIdx.x) >> 5;
    int lane = threadIdx.x & 31;
    if (gw >= NN) return;
    int beg = g_rowptr[gw], end = g_rowptr[gw + 1];
    int grp = lane >> 3;        // 0..3: which edge in the 4-pack
    int chunk = lane & 7;       // 16B chunk within the feature row

    uint4 acc;
    acc.x = acc.y = acc.z = acc.w = 0xFBFFFBFFu;   // (-65504, -65504) half2

    for (int base = beg; base < end; base += 32) {
        int cnt = min(32, end - base);
        int s = 0;
        if (lane < cnt) s = g_col[base + lane];
#pragma unroll 2
        for (int e4 = 0; e4 < cnt; e4 += 4) {
            int src_lane = e4 + grp;
            int sv = __shfl_sync(0xffffffffu, s, src_lane);
            if (src_lane < cnt) {
                uint4 v = *(const uint4*)(g_hh + sv * 32 + chunk * 4);
                acc = hmax4(acc, v);
            }
        }
    }

    // combine the 4 edge-groups (lanes differing in bits 3-4)
#pragma unroll
    for (int off = 8; off <= 16; off <<= 1) {
        uint4 o;
        o.x = __shfl_xor_sync(0xffffffffu, acc.x, off);
        o.y = __shfl_xor_sync(0xffffffffu, acc.y, off);
        o.z = __shfl_xor_sync(0xffffffffu, acc.z, off);
        o.w = __shfl_xor_sync(0xffffffffu, acc.w, off);
        acc = hmax4(acc, o);
    }

    if (beg == end) { acc.x = acc.y = acc.z = acc.w = 0u; }   // empty -> 0

    if (grp == 0)
        ((uint4*)g_aggh)[gw * 8 + chunk] = acc;
}

// ---------------- 64-wide fp32 GEMM: C = (A [+ fp16 agg]) @ W + b ----------------
// Also emits a packed fp16 shadow copy of C for the next layer's gather.
template <bool ADD>
__global__ void gemm64_kernel(const float* __restrict__ A,
                              const unsigned int* __restrict__ Ah,  // fp16x2 agg
                              const float* __restrict__ W,
                              const float* __restrict__ bias,
                              float* __restrict__ Cm,
                              unsigned int* __restrict__ Ch, int n) {
    __shared__ float As[64][68];
    __shared__ float Ws[64][68];
    int tid = threadIdx.x;
    int block_row = blockIdx.x * 64;

    for (int i = tid; i < 1024; i += 256) {
        int k = i >> 4, j4 = i & 15;
        float4 v = ((const float4*)W)[i];
        *(float4*)&Ws[k][j4 * 4] = v;
    }
    for (int i = tid; i < 1024; i += 256) {
        int m = i >> 4, k4 = i & 15;
        int row = block_row + m;
        float4 v = make_float4(0.f, 0.f, 0.f, 0.f);
        if (row < n) {
            v = ((const float4*)A)[row * 16 + k4];
            if (ADD) {
                uint2 ph = ((const uint2*)Ah)[row * 16 + k4];
                float2 u0 = __half22float2(*(__half2*)&ph.x);
                float2 u1 = __half22float2(*(__half2*)&ph.y);
                v.x += u0.x; v.y += u0.y; v.z += u1.x; v.w += u1.y;
            }
        }
        *(float4*)&As[m][k4 * 4] = v;
    }
    __syncthreads();

    int tx = tid & 15, ty = tid >> 4;
    int m0 = ty * 4, j0 = tx * 4;
    float acc[4][4];
#pragma unroll
    for (int i = 0; i < 4; i++)
#pragma unroll
        for (int j = 0; j < 4; j++) acc[i][j] = 0.f;

#pragma unroll 16
    for (int k = 0; k < 64; k++) {
        float b0 = Ws[k][j0], b1 = Ws[k][j0 + 1], b2 = Ws[k][j0 + 2], b3 = Ws[k][j0 + 3];
#pragma unroll
        for (int i = 0; i < 4; i++) {
            float a = As[m0 + i][k];
            acc[i][0] = fmaf(a, b0, acc[i][0]);
            acc[i][1] = fmaf(a, b1, acc[i][1]);
            acc[i][2] = fmaf(a, b2, acc[i][2]);
            acc[i][3] = fmaf(a, b3, acc[i][3]);
        }
    }
    float bb0 = bias[j0], bb1 = bias[j0 + 1], bb2 = bias[j0 + 2], bb3 = bias[j0 + 3];
#pragma unroll
    for (int i = 0; i < 4; i++) {
        int row = block_row + m0 + i;
        if (row < n) {
            float4 o = make_float4(acc[i][0] + bb0, acc[i][1] + bb1,
                                   acc[i][2] + bb2, acc[i][3] + bb3);
            ((float4*)Cm)[row * 16 + (j0 >> 2)] = o;
            __half2 p0 = __floats2half2_rn(o.x, o.y);
            __half2 p1 = __floats2half2_rn(o.z, o.w);
            uint2 packed = make_uint2(*(unsigned int*)&p0, *(unsigned int*)&p1);
            ((uint2*)Ch)[row * 16 + (j0 >> 2)] = packed;
        }
    }
}

// ---------------- decoder + log-softmax ----------------
__global__ void decoder_kernel(const float* __restrict__ dw,
                               const float* __restrict__ db,
                               float* __restrict__ out, int n) {
    __shared__ float Ws[HH * CC];
    __shared__ float bs[CC];
    int tid = threadIdx.x;
    for (int i = tid; i < HH * CC; i += blockDim.x) Ws[i] = dw[i];
    if (tid < CC) bs[tid] = db[tid];
    __syncthreads();
    int node = blockIdx.x * blockDim.x + tid;
    if (node >= n) return;
    float acc[CC];
#pragma unroll
    for (int c = 0; c < CC; c++) acc[c] = bs[c];
    const float4* hp = (const float4*)(g_h + node * HH);
#pragma unroll
    for (int k4 = 0; k4 < 16; k4++) {
        float4 v = hp[k4];
        int kb = k4 * 4;
#pragma unroll
        for (int c = 0; c < CC; c++)
            acc[c] += v.x * Ws[(kb + 0) * CC + c] + v.y * Ws[(kb + 1) * CC + c] +
                      v.z * Ws[(kb + 2) * CC + c] + v.w * Ws[(kb + 3) * CC + c];
    }
    float mx = acc[0];
#pragma unroll
    for (int c = 1; c < CC; c++) mx = fmaxf(mx, acc[c]);
    float s = 0.f;
#pragma unroll
    for (int c = 0; c < CC; c++) s += expf(acc[c] - mx);
    float lse = mx + logf(s);
#pragma unroll
    for (int c = 0; c < CC; c++) out[node * CC + c] = acc[c] - lse;
}

// ---------------- launch ----------------
extern "C" void kernel_launch(void* const* d_in, const int* in_sizes, int n_in,
                              void* d_out, int out_size) {
    const float* x      = (const float*)d_in[0];
    const void*  ei     = d_in[1];
    const float* enc_w  = (const float*)d_in[3];
    const float* enc_b  = (const float*)d_in[4];
    const float* proc_w = (const float*)d_in[5];
    const float* proc_b = (const float*)d_in[6];
    const float* dec_w  = (const float*)d_in[7];
    const float* dec_b  = (const float*)d_in[8];
    float* out = (float*)d_out;

    float* hptr = nullptr;
    unsigned int* hhptr = nullptr;
    unsigned int* agghptr = nullptr;
    cudaGetSymbolAddress((void**)&hptr, g_h);
    cudaGetSymbolAddress((void**)&hhptr, g_hh);
    cudaGetSymbolAddress((void**)&agghptr, g_aggh);

    const int n = NN;

    // fork: encoder GEMM runs concurrently with CSR build
    cudaStream_t s2;
    cudaStreamCreateWithFlags(&s2, cudaStreamNonBlocking);
    cudaEvent_t e0, e1;
    cudaEventCreateWithFlags(&e0, cudaEventDisableTiming);
    cudaEventCreateWithFlags(&e1, cudaEventDisableTiming);
    cudaEventRecord(e0, 0);
    cudaStreamWaitEvent(s2, e0, 0);

    // encoder on s2 (emits fp32 h + fp16 shadow)
    gemm64_kernel<false><<<(n + 63) / 64, 256, 0, s2>>>(x, nullptr, enc_w, enc_b,
                                                        hptr, hhptr, n);
    cudaEventRecord(e1, s2);

    // CSR build on capture stream
    zerodetect_kernel<<<(NN + 255) / 256, 256>>>((const unsigned int*)ei);
    convert_kernel<<<(EE + 255) / 256, 256>>>(ei);
    scan_phase1<<<SCAN_NBLK, SCAN_BLK>>>();
    scan_phase2<<<1, 128>>>();
    scan_phase3<<<SCAN_NBLK, SCAN_BLK>>>();
    scatter_kernel<<<(EE + 255) / 256, 256>>>(ei);

    // join: need both CSR and encoder before first segmax
    cudaStreamWaitEvent(0, e1, 0);

    // 6 GIN layers
    for (int it = 0; it < 6; it++) {
        segmax_kernel<<<(NN * 32 + 255) / 256, 256>>>();
        gemm64_kernel<true><<<(n + 63) / 64, 256>>>(hptr, agghptr, proc_w, proc_b,
                                                    hptr, hhptr, n);
    }

    // decoder + log-softmax
    decoder_kernel<<<(n + 127) / 128, 128>>>(dec_w, dec_b, out, n);
}

// round 11
// speedup vs baseline: 1.1260x; 1.0482x over previous
#include <cuda_runtime.h>
#include <cuda_fp16.h>
#include <math.h>
#include <float.h>

#define NN 100000
#define EE 1600000
#define HH 64
#define CC 10
#define SCAN_BLK 1024
#define SCAN_NBLK ((NN + SCAN_BLK - 1) / SCAN_BLK)   // 98

// ---------------- static device scratch ----------------
__device__ int          g_dst[EE];
__device__ int          g_col[EE];
__device__ int          g_deg[NN];
__device__ int          g_rowptr[NN + 1];
__device__ int          g_cursor[NN];
__device__ int          g_blocksum[SCAN_NBLK];
__device__ float        g_h[NN * HH];        // fp32 node features
__device__ unsigned int g_hh[NN * 32];       // fp16x2 shadow copy of h
__device__ unsigned int g_aggh[NN * 32];     // fp16x2 segment-max (exact)
__device__ int          g_odd_nonzero;

__device__ __forceinline__ uint4 hmax4(uint4 a, uint4 b) {
    uint4 r;
    *(__half2*)&r.x = __hmax2(*(__half2*)&a.x, *(__half2*)&b.x);
    *(__half2*)&r.y = __hmax2(*(__half2*)&a.y, *(__half2*)&b.y);
    *(__half2*)&r.z = __hmax2(*(__half2*)&a.z, *(__half2*)&b.z);
    *(__half2*)&r.w = __hmax2(*(__half2*)&a.w, *(__half2*)&b.w);
    return r;
}

// ---------------- setup: zero degrees + edge dtype detection ----------------
// int64 edge ids < 2^31 -> every odd 32-bit word is 0.
__global__ void zerodetect_kernel(const unsigned int* __restrict__ w) {
    int i = blockIdx.x * blockDim.x + threadIdx.x;
    if (i < NN) g_deg[i] = 0;
    if (i == 0) g_odd_nonzero = 0;
    if (i < 65536) {
        unsigned int v = w[2 * i + 1];
        if (v) atomicOr(&g_odd_nonzero, 1);
    }
}

__global__ void convert_kernel(const void* __restrict__ ei) {
    int i = blockIdx.x * blockDim.x + threadIdx.x;
    if (i >= EE) return;
    int d;
    if (g_odd_nonzero == 0) d = (int)((const long long*)ei)[EE + i];
    else                    d = ((const int*)ei)[EE + i];
    g_dst[i] = d;
    atomicAdd(&g_deg[d], 1);
}

// ---------------- multi-block exclusive scan ----------------
__global__ void scan_phase1() {
    __shared__ int warp_sums[32];
    int tid = threadIdx.x;
    int i = blockIdx.x * SCAN_BLK + tid;
    int v = (i < NN) ? g_deg[i] : 0;
    int lane = tid & 31, wid = tid >> 5;

    int incl = v;
#pragma unroll
    for (int off = 1; off < 32; off <<= 1) {
        int t = __shfl_up_sync(0xffffffffu, incl, off);
        if (lane >= off) incl += t;
    }
    if (lane == 31) warp_sums[wid] = incl;
    __syncthreads();
    if (wid == 0) {
        int ws = warp_sums[lane];
        int wincl = ws;
#pragma unroll
        for (int off = 1; off < 32; off <<= 1) {
            int t = __shfl_up_sync(0xffffffffu, wincl, off);
            if (lane >= off) wincl += t;
        }
        warp_sums[lane] = wincl - ws;
        if (lane == 31) g_blocksum[blockIdx.x] = wincl;
    }
    __syncthreads();
    int excl = incl - v + warp_sums[wid];
    if (i < NN) g_rowptr[i] = excl;
}

__global__ void scan_phase2() {
    __shared__ int ws4[4];
    __shared__ int total;
    int tid = threadIdx.x;            // 128 threads
    int v = (tid < SCAN_NBLK) ? g_blocksum[tid] : 0;
    int lane = tid & 31, wid = tid >> 5;
    int incl = v;
#pragma unroll
    for (int off = 1; off < 32; off <<= 1) {
        int t = __shfl_up_sync(0xffffffffu, incl, off);
        if (lane >= off) incl += t;
    }
    if (lane == 31) ws4[wid] = incl;
    __syncthreads();
    if (tid == 0) {
        int c = 0;
        for (int w = 0; w < 4; w++) { int t = ws4[w]; ws4[w] = c; c += t; }
        total = c;
    }
    __syncthreads();
    if (tid < SCAN_NBLK) g_blocksum[tid] = incl - v + ws4[wid];
    if (tid == 0) g_rowptr[NN] = total;
}

__global__ void scan_phase3() {
    int i = blockIdx.x * SCAN_BLK + threadIdx.x;
    if (i >= NN) return;
    int r = g_rowptr[i] + g_blocksum[blockIdx.x];
    g_rowptr[i] = r;
    g_cursor[i] = r;
}

__global__ void scatter_kernel(const void* __restrict__ ei) {
    int i = blockIdx.x * blockDim.x + threadIdx.x;
    if (i >= EE) return;
    int s;
    if (g_odd_nonzero == 0) s = (int)((const long long*)ei)[i];
    else                    s = ((const int*)ei)[i];
    int d = g_dst[i];
    int pos = atomicAdd(&g_cursor[d], 1);
    g_col[pos] = s;
}

// ---------------- segment max: 1 warp per node, 4 edges x 8 lanes ----------------
// Predicate-free inner loop via index clamping: re-maxing a duplicate edge is
// idempotent, so out-of-range lanes clamp to the last valid edge instead of
// predicating the load. unroll 4 -> 4 independent LDG.128 per lane in flight.
__global__ void segmax_kernel() {
    int gw   = (blockIdx.x * blockDim.x + threadIdx.x) >> 5;
    int lane = threadIdx.x & 31;
    if (gw >= NN) return;
    int beg = g_rowptr[gw], end = g_rowptr[gw + 1];
    int grp = lane >> 3;        // 0..3: which edge in the 4-pack
    int chunk = lane & 7;       // 16B chunk within the feature row

    uint4 acc;
    acc.x = acc.y = acc.z = acc.w = 0xFBFFFBFFu;   // (-65504, -65504) half2

    for (int base = beg; base < end; base += 32) {
        int cnt = min(32, end - base);              // >= 1 here
        int s = g_col[base + min(lane, cnt - 1)];   // clamped stage (no pred)
#pragma unroll 4
        for (int e4 = 0; e4 < cnt; e4 += 4) {
            int sl = min(e4 + grp, cnt - 1);        // clamp: duplicates are no-ops
            int sv = __shfl_sync(0xffffffffu, s, sl);
            uint4 v = *(const uint4*)(g_hh + sv * 32 + chunk * 4);
            acc = hmax4(acc, v);
        }
    }

    // combine the 4 edge-groups (lanes differing in bits 3-4)
#pragma unroll
    for (int off = 8; off <= 16; off <<= 1) {
        uint4 o;
        o.x = __shfl_xor_sync(0xffffffffu, acc.x, off);
        o.y = __shfl_xor_sync(0xffffffffu, acc.y, off);
        o.z = __shfl_xor_sync(0xffffffffu, acc.z, off);
        o.w = __shfl_xor_sync(0xffffffffu, acc.w, off);
        acc = hmax4(acc, o);
    }

    if (beg == end) { acc.x = acc.y = acc.z = acc.w = 0u; }   // empty -> 0

    if (grp == 0)
        ((uint4*)g_aggh)[gw * 8 + chunk] = acc;
}

// ---------------- 64-wide fp32 GEMM: C = (A [+ fp16 agg]) @ W + b ----------------
// Also emits a packed fp16 shadow copy of C for the next layer's gather.
template <bool ADD>
__global__ void gemm64_kernel(const float* __restrict__ A,
                              const unsigned int* __restrict__ Ah,  // fp16x2 agg
                              const float* __restrict__ W,
                              const float* __restrict__ bias,
                              float* __restrict__ Cm,
                              unsigned int* __restrict__ Ch, int n) {
    __shared__ float As[64][68];
    __shared__ float Ws[64][68];
    int tid = threadIdx.x;
    int block_row = blockIdx.x * 64;

    for (int i = tid; i < 1024; i += 256) {
        int k = i >> 4, j4 = i & 15;
        float4 v = ((const float4*)W)[i];
        *(float4*)&Ws[k][j4 * 4] = v;
    }
    for (int i = tid; i < 1024; i += 256) {
        int m = i >> 4, k4 = i & 15;
        int row = block_row + m;
        float4 v = make_float4(0.f, 0.f, 0.f, 0.f);
        if (row < n) {
            v = ((const float4*)A)[row * 16 + k4];
            if (ADD) {
                uint2 ph = ((const uint2*)Ah)[row * 16 + k4];
                float2 u0 = __half22float2(*(__half2*)&ph.x);
                float2 u1 = __half22float2(*(__half2*)&ph.y);
                v.x += u0.x; v.y += u0.y; v.z += u1.x; v.w += u1.y;
            }
        }
        *(float4*)&As[m][k4 * 4] = v;
    }
    __syncthreads();

    int tx = tid & 15, ty = tid >> 4;
    int m0 = ty * 4, j0 = tx * 4;
    float acc[4][4];
#pragma unroll
    for (int i = 0; i < 4; i++)
#pragma unroll
        for (int j = 0; j < 4; j++) acc[i][j] = 0.f;

#pragma unroll 16
    for (int k = 0; k < 64; k++) {
        float b0 = Ws[k][j0], b1 = Ws[k][j0 + 1], b2 = Ws[k][j0 + 2], b3 = Ws[k][j0 + 3];
#pragma unroll
        for (int i = 0; i < 4; i++) {
            float a = As[m0 + i][k];
            acc[i][0] = fmaf(a, b0, acc[i][0]);
            acc[i][1] = fmaf(a, b1, acc[i][1]);
            acc[i][2] = fmaf(a, b2, acc[i][2]);
            acc[i][3] = fmaf(a, b3, acc[i][3]);
        }
    }
    float bb0 = bias[j0], bb1 = bias[j0 + 1], bb2 = bias[j0 + 2], bb3 = bias[j0 + 3];
#pragma unroll
    for (int i = 0; i < 4; i++) {
        int row = block_row + m0 + i;
        if (row < n) {
            float4 o = make_float4(acc[i][0] + bb0, acc[i][1] + bb1,
                                   acc[i][2] + bb2, acc[i][3] + bb3);
            ((float4*)Cm)[row * 16 + (j0 >> 2)] = o;
            __half2 p0 = __floats2half2_rn(o.x, o.y);
            __half2 p1 = __floats2half2_rn(o.z, o.w);
            uint2 packed = make_uint2(*(unsigned int*)&p0, *(unsigned int*)&p1);
            ((uint2*)Ch)[row * 16 + (j0 >> 2)] = packed;
        }
    }
}

// ---------------- decoder + log-softmax ----------------
__global__ void decoder_kernel(const float* __restrict__ dw,
                               const float* __restrict__ db,
                               float* __restrict__ out, int n) {
    __shared__ float Ws[HH * CC];
    __shared__ float bs[CC];
    int tid = threadIdx.x;
    for (int i = tid; i < HH * CC; i += blockDim.x) Ws[i] = dw[i];
    if (tid < CC) bs[tid] = db[tid];
    __syncthreads();
    int node = blockIdx.x * blockDim.x + tid;
    if (node >= n) return;
    float acc[CC];
#pragma unroll
    for (int c = 0; c < CC; c++) acc[c] = bs[c];
    const float4* hp = (const float4*)(g_h + node * HH);
#pragma unroll
    for (int k4 = 0; k4 < 16; k4++) {
        float4 v = hp[k4];
        int kb = k4 * 4;
#pragma unroll
        for (int c = 0; c < CC; c++)
            acc[c] += v.x * Ws[(kb + 0) * CC + c] + v.y * Ws[(kb + 1) * CC + c] +
                      v.z * Ws[(kb + 2) * CC + c] + v.w * Ws[(kb + 3) * CC + c];
    }
    float mx = acc[0];
#pragma unroll
    for (int c = 1; c < CC; c++) mx = fmaxf(mx, acc[c]);
    float s = 0.f;
#pragma unroll
    for (int c = 0; c < CC; c++) s += expf(acc[c] - mx);
    float lse = mx + logf(s);
#pragma unroll
    for (int c = 0; c < CC; c++) out[node * CC + c] = acc[c] - lse;
}

// ---------------- launch ----------------
extern "C" void kernel_launch(void* const* d_in, const int* in_sizes, int n_in,
                              void* d_out, int out_size) {
    const float* x      = (const float*)d_in[0];
    const void*  ei     = d_in[1];
    const float* enc_w  = (const float*)d_in[3];
    const float* enc_b  = (const float*)d_in[4];
    const float* proc_w = (const float*)d_in[5];
    const float* proc_b = (const float*)d_in[6];
    const float* dec_w  = (const float*)d_in[7];
    const float* dec_b  = (const float*)d_in[8];
    float* out = (float*)d_out;

    float* hptr = nullptr;
    unsigned int* hhptr = nullptr;
    unsigned int* agghptr = nullptr;
    cudaGetSymbolAddress((void**)&hptr, g_h);
    cudaGetSymbolAddress((void**)&hhptr, g_hh);
    cudaGetSymbolAddress((void**)&agghptr, g_aggh);

    const int n = NN;

    // fork: encoder GEMM runs concurrently with CSR build
    cudaStream_t s2;
    cudaStreamCreateWithFlags(&s2, cudaStreamNonBlocking);
    cudaEvent_t e0, e1;
    cudaEventCreateWithFlags(&e0, cudaEventDisableTiming);
    cudaEventCreateWithFlags(&e1, cudaEventDisableTiming);
    cudaEventRecord(e0, 0);
    cudaStreamWaitEvent(s2, e0, 0);

    // encoder on s2 (emits fp32 h + fp16 shadow)
    gemm64_kernel<false><<<(n + 63) / 64, 256, 0, s2>>>(x, nullptr, enc_w, enc_b,
                                                        hptr, hhptr, n);
    cudaEventRecord(e1, s2);

    // CSR build on capture stream
    zerodetect_kernel<<<(NN + 255) / 256, 256>>>((const unsigned int*)ei);
    convert_kernel<<<(EE + 255) / 256, 256>>>(ei);
    scan_phase1<<<SCAN_NBLK, SCAN_BLK>>>();
    scan_phase2<<<1, 128>>>();
    scan_phase3<<<SCAN_NBLK, SCAN_BLK>>>();
    scatter_kernel<<<(EE + 255) / 256, 256>>>(ei);

    // join: need both CSR and encoder before first segmax
    cudaStreamWaitEvent(0, e1, 0);

    // 6 GIN layers
    for (int it = 0; it < 6; it++) {
        segmax_kernel<<<(NN * 32 + 255) / 256, 256>>>();
        gemm64_kernel<true><<<(n + 63) / 64, 256>>>(hptr, agghptr, proc_w, proc_b,
                                                    hptr, hhptr, n);
    }

    // decoder + log-softmax
    decoder_kernel<<<(n + 127) / 128, 128>>>(dec_w, dec_b, out, n);
}

// round 12
// speedup vs baseline: 1.4770x; 1.3117x over previous
#include <cuda_runtime.h>
#include <cuda_fp16.h>
#include <math.h>
#include <float.h>

#define NN 100000
#define EE 1600000
#define HH 64
#define CC 10
#define SCAN_BLK 1024
#define SCAN_NBLK ((NN + SCAN_BLK - 1) / SCAN_BLK)   // 98

// ---------------- static device scratch ----------------
__device__ int          g_dst[EE];
__device__ int          g_col[EE];
__device__ int          g_deg[NN];
__device__ int          g_rowptr[NN + 1];
__device__ int          g_cursor[NN];
__device__ int          g_blocksum[SCAN_NBLK];
__device__ unsigned int g_hh[NN * 32];       // fp16x2 node features (the only h)
__device__ unsigned int g_aggh[NN * 32];     // fp16x2 segment-max
__device__ int          g_odd_nonzero;

__device__ __forceinline__ uint4 hmax4(uint4 a, uint4 b) {
    uint4 r;
    *(__half2*)&r.x = __hmax2(*(__half2*)&a.x, *(__half2*)&b.x);
    *(__half2*)&r.y = __hmax2(*(__half2*)&a.y, *(__half2*)&b.y);
    *(__half2*)&r.z = __hmax2(*(__half2*)&a.z, *(__half2*)&b.z);
    *(__half2*)&r.w = __hmax2(*(__half2*)&a.w, *(__half2*)&b.w);
    return r;
}
__device__ __forceinline__ uint4 hadd4(uint4 a, uint4 b) {
    uint4 r;
    *(__half2*)&r.x = __hadd2(*(__half2*)&a.x, *(__half2*)&b.x);
    *(__half2*)&r.y = __hadd2(*(__half2*)&a.y, *(__half2*)&b.y);
    *(__half2*)&r.z = __hadd2(*(__half2*)&a.z, *(__half2*)&b.z);
    *(__half2*)&r.w = __hadd2(*(__half2*)&a.w, *(__half2*)&b.w);
    return r;
}

__device__ __forceinline__ void ldm_x4(unsigned& r0, unsigned& r1,
                                       unsigned& r2, unsigned& r3, unsigned addr) {
    asm volatile("ldmatrix.sync.aligned.m8n8.x4.shared.b16 {%0,%1,%2,%3}, [%4];"
                 : "=r"(r0), "=r"(r1), "=r"(r2), "=r"(r3) : "r"(addr));
}
__device__ __forceinline__ void ldm_x2t(unsigned& r0, unsigned& r1, unsigned addr) {
    asm volatile("ldmatrix.sync.aligned.m8n8.x2.trans.shared.b16 {%0,%1}, [%2];"
                 : "=r"(r0), "=r"(r1) : "r"(addr));
}
__device__ __forceinline__ void mma_f16(float c[4], unsigned a0, unsigned a1,
                                        unsigned a2, unsigned a3,
                                        unsigned b0, unsigned b1) {
    asm volatile("mma.sync.aligned.m16n8k16.row.col.f32.f16.f16.f32 "
                 "{%0,%1,%2,%3},{%4,%5,%6,%7},{%8,%9},{%0,%1,%2,%3};"
                 : "+f"(c[0]), "+f"(c[1]), "+f"(c[2]), "+f"(c[3])
                 : "r"(a0), "r"(a1), "r"(a2), "r"(a3), "r"(b0), "r"(b1));
}

// ---------------- setup: zero degrees + edge dtype detection ----------------
__global__ void zerodetect_kernel(const unsigned int* __restrict__ w) {
    int i = blockIdx.x * blockDim.x + threadIdx.x;
    if (i < NN) g_deg[i] = 0;
    if (i == 0) g_odd_nonzero = 0;
    if (i < 65536) {
        unsigned int v = w[2 * i + 1];
        if (v) atomicOr(&g_odd_nonzero, 1);
    }
}

__global__ void convert_kernel(const void* __restrict__ ei) {
    int i = blockIdx.x * blockDim.x + threadIdx.x;
    if (i >= EE) return;
    int d;
    if (g_odd_nonzero == 0) d = (int)((const long long*)ei)[EE + i];
    else                    d = ((const int*)ei)[EE + i];
    g_dst[i] = d;
    atomicAdd(&g_deg[d], 1);
}

// ---------------- multi-block exclusive scan ----------------
__global__ void scan_phase1() {
    __shared__ int warp_sums[32];
    int tid = threadIdx.x;
    int i = blockIdx.x * SCAN_BLK + tid;
    int v = (i < NN) ? g_deg[i] : 0;
    int lane = tid & 31, wid = tid >> 5;
    int incl = v;
#pragma unroll
    for (int off = 1; off < 32; off <<= 1) {
        int t = __shfl_up_sync(0xffffffffu, incl, off);
        if (lane >= off) incl += t;
    }
    if (lane == 31) warp_sums[wid] = incl;
    __syncthreads();
    if (wid == 0) {
        int ws = warp_sums[lane];
        int wincl = ws;
#pragma unroll
        for (int off = 1; off < 32; off <<= 1) {
            int t = __shfl_up_sync(0xffffffffu, wincl, off);
            if (lane >= off) wincl += t;
        }
        warp_sums[lane] = wincl - ws;
        if (lane == 31) g_blocksum[blockIdx.x] = wincl;
    }
    __syncthreads();
    int excl = incl - v + warp_sums[wid];
    if (i < NN) g_rowptr[i] = excl;
}

__global__ void scan_phase2() {
    __shared__ int ws4[4];
    __shared__ int total;
    int tid = threadIdx.x;            // 128 threads
    int v = (tid < SCAN_NBLK) ? g_blocksum[tid] : 0;
    int lane = tid & 31, wid = tid >> 5;
    int incl = v;
#pragma unroll
    for (int off = 1; off < 32; off <<= 1) {
        int t = __shfl_up_sync(0xffffffffu, incl, off);
        if (lane >= off) incl += t;
    }
    if (lane == 31) ws4[wid] = incl;
    __syncthreads();
    if (tid == 0) {
        int c = 0;
        for (int w = 0; w < 4; w++) { int t = ws4[w]; ws4[w] = c; c += t; }
        total = c;
    }
    __syncthreads();
    if (tid < SCAN_NBLK) g_blocksum[tid] = incl - v + ws4[wid];
    if (tid == 0) g_rowptr[NN] = total;
}

__global__ void scan_phase3() {
    int i = blockIdx.x * SCAN_BLK + threadIdx.x;
    if (i >= NN) return;
    int r = g_rowptr[i] + g_blocksum[blockIdx.x];
    g_rowptr[i] = r;
    g_cursor[i] = r;
}

__global__ void scatter_kernel(const void* __restrict__ ei) {
    int i = blockIdx.x * blockDim.x + threadIdx.x;
    if (i >= EE) return;
    int s;
    if (g_odd_nonzero == 0) s = (int)((const long long*)ei)[i];
    else                    s = ((const int*)ei)[i];
    int d = g_dst[i];
    int pos = atomicAdd(&g_cursor[d], 1);
    g_col[pos] = s;
}

// ---------------- segment max: 1 warp per node, 4 edges x 8 lanes ----------------
__global__ void segmax_kernel() {
    int gw   = (blockIdx.x * blockDim.x + threadIdx.x) >> 5;
    int lane = threadIdx.x & 31;
    if (gw >= NN) return;
    int beg = g_rowptr[gw], end = g_rowptr[gw + 1];
    int grp = lane >> 3;
    int chunk = lane & 7;

    uint4 acc;
    acc.x = acc.y = acc.z = acc.w = 0xFBFFFBFFu;   // (-65504, -65504) half2

    for (int base = beg; base < end; base += 32) {
        int cnt = min(32, end - base);
        int s = g_col[base + min(lane, cnt - 1)];
#pragma unroll 4
        for (int e4 = 0; e4 < cnt; e4 += 4) {
            int sl = min(e4 + grp, cnt - 1);
            int sv = __shfl_sync(0xffffffffu, s, sl);
            uint4 v = *(const uint4*)(g_hh + sv * 32 + chunk * 4);
            acc = hmax4(acc, v);
        }
    }
#pragma unroll
    for (int off = 8; off <= 16; off <<= 1) {
        uint4 o;
        o.x = __shfl_xor_sync(0xffffffffu, acc.x, off);
        o.y = __shfl_xor_sync(0xffffffffu, acc.y, off);
        o.z = __shfl_xor_sync(0xffffffffu, acc.z, off);
        o.w = __shfl_xor_sync(0xffffffffu, acc.w, off);
        acc = hmax4(acc, o);
    }
    if (beg == end) { acc.x = acc.y = acc.z = acc.w = 0u; }
    if (grp == 0)
        ((uint4*)g_aggh)[gw * 8 + chunk] = acc;
}

// ---------------- fp16 tensor-core GEMM: hh_out = (A) @ W + b ----------------
// ENC=true:  A = fp32 x, converted to fp16.
// ENC=false: A = hh + aggh (fp16 add).
// W split into Whi + Wlo fp16 (W error ~2^-22); fp32 accumulate; 2 MMAs per frag.
// 64x64 tile, 256 threads = 8 warps (4 m-warps x 2 n-warps), m16n8k16.
template <bool ENC>
__global__ void __launch_bounds__(256)
gemm_h16_kernel(const float* __restrict__ Ax,
                const unsigned* __restrict__ Hh,
                const unsigned* __restrict__ Aggh,
                const float* __restrict__ W,
                const float* __restrict__ bias,
                unsigned* __restrict__ OutHh, int n) {
    __shared__ __align__(16) __half As[64 * 72];
    __shared__ __align__(16) __half WsH[64 * 72];
    __shared__ __align__(16) __half WsL[64 * 72];

    int tid = threadIdx.x;
    int block_row = blockIdx.x * 64;

    // stage W hi/lo split (k-major [64][64])
    for (int i = tid; i < 1024; i += 256) {
        int k = i >> 4, c4 = i & 15;
        float4 v = ((const float4*)W)[i];
        __half h0 = __float2half_rn(v.x), h1 = __float2half_rn(v.y);
        __half h2 = __float2half_rn(v.z), h3 = __float2half_rn(v.w);
        __half l0 = __float2half_rn(v.x - __half2float(h0));
        __half l1 = __float2half_rn(v.y - __half2float(h1));
        __half l2 = __float2half_rn(v.z - __half2float(h2));
        __half l3 = __float2half_rn(v.w - __half2float(h3));
        __half* ph = &WsH[k * 72 + c4 * 4];
        ph[0] = h0; ph[1] = h1; ph[2] = h2; ph[3] = h3;
        __half* pl = &WsL[k * 72 + c4 * 4];
        pl[0] = l0; pl[1] = l1; pl[2] = l2; pl[3] = l3;
    }

    // stage A
    if (ENC) {
        for (int i = tid; i < 1024; i += 256) {
            int m = i >> 4, c = i & 15;
            int row = block_row + m;
            float4 v = make_float4(0.f, 0.f, 0.f, 0.f);
            if (row < n) v = ((const float4*)Ax)[row * 16 + c];
            __half* p = &As[m * 72 + c * 4];
            p[0] = __float2half_rn(v.x); p[1] = __float2half_rn(v.y);
            p[2] = __float2half_rn(v.z); p[3] = __float2half_rn(v.w);
        }
    } else {
        for (int i = tid; i < 512; i += 256) {
            int m = i >> 3, c4 = i & 7;       // uint4 = 8 halfs
            int row = block_row + m;
            uint4 v = make_uint4(0u, 0u, 0u, 0u);
            if (row < n) {
                uint4 hv = ((const uint4*)Hh)[row * 8 + c4];
                uint4 av = ((const uint4*)Aggh)[row * 8 + c4];
                v = hadd4(hv, av);
            }
            *(uint4*)&As[m * 72 + c4 * 8] = v;
        }
    }
    __syncthreads();

    int lane = tid & 31, wid = tid >> 5;
    int m0 = (wid & 3) * 16;
    int n0 = (wid >> 2) * 32;

    unsigned sAs = (unsigned)__cvta_generic_to_shared(As);
    unsigned sWH = (unsigned)__cvta_generic_to_shared(WsH);
    unsigned sWL = (unsigned)__cvta_generic_to_shared(WsL);

    // ldmatrix lane addressing
    int a_row = m0 + ((lane >> 3) & 1) * 8 + (lane & 7);
    int a_k   = ((lane >> 4) & 1) * 8;
    unsigned a_addr = sAs + (a_row * 72 + a_k) * 2;
    int b_k = lane & 15;                       // rows of B (k dim)

    float c[4][4];
#pragma unroll
    for (int i = 0; i < 4; i++)
#pragma unroll
        for (int j = 0; j < 4; j++) c[i][j] = 0.f;

#pragma unroll
    for (int ks = 0; ks < 4; ks++) {
        unsigned a0, a1, a2, a3;
        ldm_x4(a0, a1, a2, a3, a_addr + ks * 32);          // +16 halfs per kstep
        unsigned brow = ((ks * 16 + b_k) * 72 + n0) * 2;
#pragma unroll
        for (int nt = 0; nt < 4; nt++) {
            unsigned bh0, bh1, bl0, bl1;
            ldm_x2t(bh0, bh1, sWH + brow + nt * 16);
            ldm_x2t(bl0, bl1, sWL + brow + nt * 16);
            mma_f16(c[nt], a0, a1, a2, a3, bh0, bh1);
            mma_f16(c[nt], a0, a1, a2, a3, bl0, bl1);
        }
    }

    // epilogue: bias + fp16 store
    int g2 = lane >> 2, t = lane & 3;
#pragma unroll
    for (int nt = 0; nt < 4; nt++) {
        int col = n0 + nt * 8 + 2 * t;
        float2 bb = *(const float2*)&bias[col];
        int r0 = block_row + m0 + g2;
        int r1 = r0 + 8;
        if (r0 < n) {
            __half2 p = __floats2half2_rn(c[nt][0] + bb.x, c[nt][1] + bb.y);
            OutHh[r0 * 32 + (col >> 1)] = *(unsigned*)&p;
        }
        if (r1 < n) {
            __half2 p = __floats2half2_rn(c[nt][2] + bb.x, c[nt][3] + bb.y);
            OutHh[r1 * 32 + (col >> 1)] = *(unsigned*)&p;
        }
    }
}

// ---------------- decoder + log-softmax (fp16 h input) ----------------
__global__ void decoder_kernel(const unsigned* __restrict__ Hh,
                               const float* __restrict__ dw,
                               const float* __restrict__ db,
                               float* __restrict__ out, int n) {
    __shared__ float Ws[HH * CC];
    __shared__ float bs[CC];
    int tid = threadIdx.x;
    for (int i = tid; i < HH * CC; i += blockDim.x) Ws[i] = dw[i];
    if (tid < CC) bs[tid] = db[tid];
    __syncthreads();
    int node = blockIdx.x * blockDim.x + tid;
    if (node >= n) return;
    float acc[CC];
#pragma unroll
    for (int c = 0; c < CC; c++) acc[c] = bs[c];
    const unsigned* hp = Hh + node * 32;
#pragma unroll
    for (int k2 = 0; k2 < 32; k2++) {
        unsigned pv = hp[k2];
        float2 v = __half22float2(*(__half2*)&pv);
        int kb = k2 * 2;
#pragma unroll
        for (int c = 0; c < CC; c++)
            acc[c] += v.x * Ws[(kb + 0) * CC + c] + v.y * Ws[(kb + 1) * CC + c];
    }
    float mx = acc[0];
#pragma unroll
    for (int c = 1; c < CC; c++) mx = fmaxf(mx, acc[c]);
    float s = 0.f;
#pragma unroll
    for (int c = 0; c < CC; c++) s += expf(acc[c] - mx);
    float lse = mx + logf(s);
#pragma unroll
    for (int c = 0; c < CC; c++) out[node * CC + c] = acc[c] - lse;
}

// ---------------- launch ----------------
extern "C" void kernel_launch(void* const* d_in, const int* in_sizes, int n_in,
                              void* d_out, int out_size) {
    const float* x      = (const float*)d_in[0];
    const void*  ei     = d_in[1];
    const float* enc_w  = (const float*)d_in[3];
    const float* enc_b  = (const float*)d_in[4];
    const float* proc_w = (const float*)d_in[5];
    const float* proc_b = (const float*)d_in[6];
    const float* dec_w  = (const float*)d_in[7];
    const float* dec_b  = (const float*)d_in[8];
    float* out = (float*)d_out;

    unsigned* hhptr = nullptr;
    unsigned* agghptr = nullptr;
    cudaGetSymbolAddress((void**)&hhptr, g_hh);
    cudaGetSymbolAddress((void**)&agghptr, g_aggh);

    const int n = NN;
    const int ggrid = (n + 63) / 64;

    // fork: encoder GEMM runs concurrently with CSR build
    cudaStream_t s2;
    cudaStreamCreateWithFlags(&s2, cudaStreamNonBlocking);
    cudaEvent_t e0, e1;
    cudaEventCreateWithFlags(&e0, cudaEventDisableTiming);
    cudaEventCreateWithFlags(&e1, cudaEventDisableTiming);
    cudaEventRecord(e0, 0);
    cudaStreamWaitEvent(s2, e0, 0);

    // encoder on s2 (fp32 x -> fp16 h)
    gemm_h16_kernel<true><<<ggrid, 256, 0, s2>>>(x, nullptr, nullptr,
                                                 enc_w, enc_b, hhptr, n);
    cudaEventRecord(e1, s2);

    // CSR build on capture stream
    zerodetect_kernel<<<(NN + 255) / 256, 256>>>((const unsigned int*)ei);
    convert_kernel<<<(EE + 255) / 256, 256>>>(ei);
    scan_phase1<<<SCAN_NBLK, SCAN_BLK>>>();
    scan_phase2<<<1, 128>>>();
    scan_phase3<<<SCAN_NBLK, SCAN_BLK>>>();
    scatter_kernel<<<(EE + 255) / 256, 256>>>(ei);

    // join
    cudaStreamWaitEvent(0, e1, 0);

    // 6 GIN layers
    for (int it = 0; it < 6; it++) {
        segmax_kernel<<<(NN * 32 + 255) / 256, 256>>>();
        gemm_h16_kernel<false><<<ggrid, 256>>>(nullptr, hhptr, agghptr,
                                               proc_w, proc_b, hhptr, n);
    }

    // decoder + log-softmax
    decoder_kernel<<<(n + 127) / 128, 128>>>(hhptr, dec_w, dec_b, out, n);
}